// round 17
// baseline (speedup 1.0000x reference)
#include <cuda_runtime.h>
#include <cuda_fp16.h>
#include <cstdint>
#include <math.h>

#define B_   2
#define T_   2048
#define C_   1024
#define NH_  16
#define HS_  64
#define WIN_ 256

// ---------------------------------------------------------------------------
// Scratch (__device__ globals; no allocation allowed)
// ---------------------------------------------------------------------------
__device__ __half g_qkv[(size_t)B_ * T_ * 3 * C_];    // quantized qkv
__device__ __half g_xq[(size_t)B_ * T_ * C_];         // quantized x
__device__ __half g_yq[(size_t)B_ * T_ * C_];         // quantized y (from swa)
__device__ __half g_wa[(size_t)3 * C_ * C_];          // W_attn^T [3C, C] fp16
__device__ __half g_wp[(size_t)C_ * C_];              // W_proj^T [C, C]  fp16

// ---------------------------------------------------------------------------
// mma.sync / ldmatrix / cp.async helpers
// ---------------------------------------------------------------------------
__device__ __forceinline__ uint32_t smem_to_u32(const void* smem_ptr) {
    uint32_t addr;
    asm("{ .reg .u64 tmp; cvta.to.shared.u64 tmp, %1; cvt.u32.u64 %0, tmp; }"
        : "=r"(addr) : "l"(smem_ptr));
    return addr;
}
__device__ __forceinline__ void cp16(uint32_t saddr, const void* g) {
    asm volatile("cp.async.cg.shared.global [%0], [%1], 16;" :: "r"(saddr), "l"(g));
}
__device__ __forceinline__ void cp_commit() {
    asm volatile("cp.async.commit_group;" ::: "memory");
}
template <int N>
__device__ __forceinline__ void cp_wait() {
    asm volatile("cp.async.wait_group %0;" :: "n"(N) : "memory");
}
__device__ __forceinline__ void ldm4(uint32_t* r, uint32_t addr) {
    asm volatile("ldmatrix.sync.aligned.m8n8.x4.shared.b16 {%0,%1,%2,%3}, [%4];"
        : "=r"(r[0]), "=r"(r[1]), "=r"(r[2]), "=r"(r[3]) : "r"(addr));
}
__device__ __forceinline__ void ldm4t(uint32_t* r, uint32_t addr) {
    asm volatile("ldmatrix.sync.aligned.m8n8.x4.trans.shared.b16 {%0,%1,%2,%3}, [%4];"
        : "=r"(r[0]), "=r"(r[1]), "=r"(r[2]), "=r"(r[3]) : "r"(addr));
}
__device__ __forceinline__ void mma_f16(float* c, const uint32_t* a, const uint32_t* b) {
    asm volatile("mma.sync.aligned.m16n8k16.row.col.f32.f16.f16.f32 "
        "{%0,%1,%2,%3}, {%4,%5,%6,%7}, {%8,%9}, {%0,%1,%2,%3};"
        : "+f"(c[0]), "+f"(c[1]), "+f"(c[2]), "+f"(c[3])
        : "r"(a[0]), "r"(a[1]), "r"(a[2]), "r"(a[3]), "r"(b[0]), "r"(b[1]));
}

// ---------------------------------------------------------------------------
// Fused prep: x quant + W_attn transpose-quant + W_proj transpose-quant.
// ---------------------------------------------------------------------------
#define QB_BLOCKS 8192
#define WA_BLOCKS (96 * 32)
#define WP_BLOCKS (32 * 32)
#define PREP_BLOCKS (QB_BLOCKS + WA_BLOCKS + WP_BLOCKS)

__device__ __forceinline__ void transpose_tile(const float* __restrict__ in,
                                               __half* __restrict__ oq,
                                               int K, int N, int ntile, int ktile,
                                               int tid, float* t /*[32*33]*/)
{
    const int nt = ntile * 32;
    const int kt = ktile * 32;
    const int tx = tid & 31;
    const int ty = tid >> 5;
#pragma unroll
    for (int j = 0; j < 4; j++) {
        int k = kt + ty + j * 8;
        t[(ty + j * 8) * 33 + tx] = in[(size_t)k * N + nt + tx];
    }
    __syncthreads();
#pragma unroll
    for (int j = 0; j < 4; j++) {
        int n = nt + ty + j * 8;
        int k = kt + tx;
        oq[(size_t)n * K + k] = __float2half(t[tx * 33 + ty + j * 8]);
    }
}

__global__ __launch_bounds__(256) void prep_all(const float* __restrict__ x,
                                                const float* __restrict__ W_attn,
                                                const float* __restrict__ W_proj,
                                                __half* __restrict__ xq,
                                                __half* __restrict__ wa,
                                                __half* __restrict__ wp)
{
    __shared__ float t[32 * 33];
    const int bid = blockIdx.x;
    const int tid = threadIdx.x;
    if (bid < QB_BLOCKS) {
        const int i = bid * 256 + tid;
        float2 v = reinterpret_cast<const float2*>(x)[i];
        reinterpret_cast<__half2*>(xq)[i] = __floats2half2_rn(v.x, v.y);
    } else if (bid < QB_BLOCKS + WA_BLOCKS) {
        const int idx = bid - QB_BLOCKS;
        transpose_tile(W_attn, wa, C_, 3 * C_, idx % 96, idx / 96, tid, t);
    } else {
        const int idx = bid - (QB_BLOCKS + WA_BLOCKS);
        transpose_tile(W_proj, wp, C_, C_, idx % 32, idx / 32, tid, t);
    }
}

// ---------------------------------------------------------------------------
// Shared gemm constants
// ---------------------------------------------------------------------------
#define BKC 64
#define LDA 72
#define ROW_BYTES (LDA * 2)                  // 144

// ---------------------------------------------------------------------------
// GEMM A (QKV, big grid): CTA 128x128, 128 threads, 4 warps (2Mx2N),
// warp tile 64x64, 2-stage cp.async, 3 CTAs/SM. fp16 quantized output.
// ---------------------------------------------------------------------------
#define A64_TILE (128 * ROW_BYTES)           // 18432
#define A64_STAGE (2 * A64_TILE)             // 36864 (A + B tiles)
#define A64_SMEM (2 * A64_STAGE)             // 73728

__global__ __launch_bounds__(128, 3) void gemm_w64(
    const __half* __restrict__ Aq, const __half* __restrict__ Bq,
    __half* __restrict__ Cq, int M, int N, int K)
{
    extern __shared__ char smem[];
    const uint32_t sbase = smem_to_u32(smem);

    const int tid  = threadIdx.x;
    const int lane = tid & 31;
    const int wid  = tid >> 5;
    const int warpRow = wid & 1;
    const int warpCol = wid >> 1;
    const int m0 = blockIdx.y * 128;
    const int n0 = blockIdx.x * 128;
    const int NC = K / BKC;

    float acc[4][8][4];
#pragma unroll
    for (int mt = 0; mt < 4; mt++)
#pragma unroll
        for (int nt = 0; nt < 8; nt++)
#pragma unroll
            for (int e = 0; e < 4; e++) acc[mt][nt][e] = 0.0f;

    const uint32_t a_row   = (uint32_t)(warpRow * 64 + (lane & 15));
    const uint32_t a_kof   = (uint32_t)((lane >> 4) << 3);
    const uint32_t b_rbase = (uint32_t)(warpCol * 64 + (lane & 7) + ((lane & 16) >> 1));
    const uint32_t b_kof   = (uint32_t)(lane & 8);

    auto load_stage = [&](int stg, int kk) {
        const uint32_t sb = sbase + stg * A64_STAGE;
#pragma unroll
        for (int i = 0; i < 8; i++) {
            const int v = tid + i * 128;
            const int row = v >> 3, seg = v & 7;
            const uint32_t so = (uint32_t)(row * LDA + seg * 8) * 2;
            cp16(sb + so, Aq + (size_t)(m0 + row) * K + kk + seg * 8);
            cp16(sb + A64_TILE + so, Bq + (size_t)(n0 + row) * K + kk + seg * 8);
        }
        cp_commit();
    };

    load_stage(0, 0);

    for (int c = 0; c < NC; c++) {
        const int buf = c & 1;
        if (c + 1 < NC) {
            load_stage(buf ^ 1, (c + 1) * BKC);
            cp_wait<1>();
        } else {
            cp_wait<0>();
        }
        __syncthreads();

        const uint32_t sb = sbase + buf * A64_STAGE;

#pragma unroll
        for (int ks = 0; ks < 4; ks++) {
            const uint32_t akc = (uint32_t)(ks * 16) + a_kof;
            const uint32_t bkc = (uint32_t)(ks * 16) + b_kof;

            uint32_t fA[4][4];
#pragma unroll
            for (int mt = 0; mt < 4; mt++) {
                const uint32_t off = ((a_row + mt * 16) * LDA + akc) * 2;
                ldm4(fA[mt], sb + off);
            }
            uint32_t fB[4][4];
#pragma unroll
            for (int g = 0; g < 4; g++) {
                const uint32_t off = ((b_rbase + g * 16) * LDA + bkc) * 2;
                ldm4(fB[g], sb + A64_TILE + off);
            }

#pragma unroll
            for (int mt = 0; mt < 4; mt++) {
#pragma unroll
                for (int nt = 0; nt < 8; nt++) {
                    mma_f16(acc[mt][nt], fA[mt], &fB[nt >> 1][(nt & 1) * 2]);
                }
            }
        }
        __syncthreads();
    }

    const int erow = m0 + warpRow * 64 + (lane >> 2);
    const int ecol = n0 + warpCol * 64 + (lane & 3) * 2;
#pragma unroll
    for (int mt = 0; mt < 4; mt++) {
#pragma unroll
        for (int nt = 0; nt < 8; nt++) {
            const size_t i0 = (size_t)(erow + mt * 16) * N + ecol + nt * 8;
            const size_t i1 = (size_t)(erow + mt * 16 + 8) * N + ecol + nt * 8;
            *reinterpret_cast<__half2*>(Cq + i0) =
                __floats2half2_rn(acc[mt][nt][0], acc[mt][nt][1]);
            *reinterpret_cast<__half2*>(Cq + i1) =
                __floats2half2_rn(acc[mt][nt][2], acc[mt][nt][3]);
        }
    }
}

// ---------------------------------------------------------------------------
// GEMM P (proj, parallelism-bound): CTA 64x128, 128 threads, 4 warps (1Mx4N),
// warp tile 64x32, 2-stage cp.async, 4 CTAs/SM. 512 CTAs. fp32 output.
// ---------------------------------------------------------------------------
#define P_A_TILE (64 * ROW_BYTES)            // 9216
#define P_B_TILE (128 * ROW_BYTES)           // 18432
#define P_STAGE (P_A_TILE + P_B_TILE)        // 27648
#define P_SMEM (2 * P_STAGE)                 // 55296

__global__ __launch_bounds__(128, 4) void gemm_proj(
    const __half* __restrict__ Aq, const __half* __restrict__ Bq,
    float* __restrict__ C, int M, int N, int K)
{
    extern __shared__ char smem[];
    const uint32_t sbase = smem_to_u32(smem);

    const int tid  = threadIdx.x;
    const int lane = tid & 31;
    const int wid  = tid >> 5;          // warpCol 0..3
    const int m0 = blockIdx.y * 64;
    const int n0 = blockIdx.x * 128;
    const int NC = K / BKC;

    float acc[4][4][4];
#pragma unroll
    for (int mt = 0; mt < 4; mt++)
#pragma unroll
        for (int nt = 0; nt < 4; nt++)
#pragma unroll
            for (int e = 0; e < 4; e++) acc[mt][nt][e] = 0.0f;

    const uint32_t a_row = (uint32_t)(lane & 15);
    const uint32_t a_kof = (uint32_t)((lane >> 4) << 3);
    const uint32_t b_row = (uint32_t)(wid * 32 + (lane & 7) + ((lane & 16) >> 1));
    const uint32_t b_kof = (uint32_t)(lane & 8);

    auto load_stage = [&](int stg, int kk) {
        const uint32_t sb = sbase + stg * P_STAGE;
        // A: 64 rows x 8 segs = 512 vec (4/thread)
#pragma unroll
        for (int i = 0; i < 4; i++) {
            const int v = tid + i * 128;
            const int row = v >> 3, seg = v & 7;
            const uint32_t so = (uint32_t)(row * LDA + seg * 8) * 2;
            cp16(sb + so, Aq + (size_t)(m0 + row) * K + kk + seg * 8);
        }
        // B: 128 rows x 8 segs = 1024 vec (8/thread)
#pragma unroll
        for (int i = 0; i < 8; i++) {
            const int v = tid + i * 128;
            const int row = v >> 3, seg = v & 7;
            const uint32_t so = (uint32_t)(row * LDA + seg * 8) * 2;
            cp16(sb + P_A_TILE + so, Bq + (size_t)(n0 + row) * K + kk + seg * 8);
        }
        cp_commit();
    };

    load_stage(0, 0);

    for (int c = 0; c < NC; c++) {
        const int buf = c & 1;
        if (c + 1 < NC) {
            load_stage(buf ^ 1, (c + 1) * BKC);
            cp_wait<1>();
        } else {
            cp_wait<0>();
        }
        __syncthreads();

        const uint32_t sb = sbase + buf * P_STAGE;

#pragma unroll
        for (int ks = 0; ks < 4; ks++) {
            const uint32_t akc = (uint32_t)(ks * 16) + a_kof;
            const uint32_t bkc = (uint32_t)(ks * 16) + b_kof;

            uint32_t fA[4][4];
#pragma unroll
            for (int mt = 0; mt < 4; mt++) {
                const uint32_t off = ((a_row + mt * 16) * LDA + akc) * 2;
                ldm4(fA[mt], sb + off);
            }
            uint32_t fB[2][4];
#pragma unroll
            for (int g = 0; g < 2; g++) {
                const uint32_t off = ((b_row + g * 16) * LDA + bkc) * 2;
                ldm4(fB[g], sb + P_A_TILE + off);
            }

#pragma unroll
            for (int mt = 0; mt < 4; mt++) {
#pragma unroll
                for (int nt = 0; nt < 4; nt++) {
                    mma_f16(acc[mt][nt], fA[mt], &fB[nt >> 1][(nt & 1) * 2]);
                }
            }
        }
        __syncthreads();
    }

    const int erow = m0 + (lane >> 2);
    const int ecol = n0 + wid * 32 + (lane & 3) * 2;
#pragma unroll
    for (int mt = 0; mt < 4; mt++) {
#pragma unroll
        for (int nt = 0; nt < 4; nt++) {
            const size_t i0 = (size_t)(erow + mt * 16) * N + ecol + nt * 8;
            const size_t i1 = (size_t)(erow + mt * 16 + 8) * N + ecol + nt * 8;
            *reinterpret_cast<float2*>(C + i0) = make_float2(acc[mt][nt][0], acc[mt][nt][1]);
            *reinterpret_cast<float2*>(C + i1) = make_float2(acc[mt][nt][2], acc[mt][nt][3]);
        }
    }
}

// ---------------------------------------------------------------------------
// Tensor-core SWA flash attention — pure 1-product fp16 (proven).
// ---------------------------------------------------------------------------
#define SWA_LDT 72
#define SWA_TILE_B (64 * SWA_LDT * 2)     // 9216
#define SWA_SMEM (3 * SWA_TILE_B)         // 27648

__global__ __launch_bounds__(128, 4) void swa_mma(const __half* __restrict__ qkv,
                                                  __half* __restrict__ yq)
{
    extern __shared__ char sm[];
    const uint32_t sb = smem_to_u32(sm);
    const uint32_t QH = sb;
    const uint32_t KH = sb + 1 * SWA_TILE_B;
    const uint32_t VH = sb + 2 * SWA_TILE_B;

    const int qt   = blockIdx.x;
    const int h    = blockIdx.y;
    const int b    = blockIdx.z;
    const int tid  = threadIdx.x;
    const int lane = tid & 31;
    const int w    = tid >> 5;

    const size_t st = 3 * C_;
    const __half* baseh = qkv + (size_t)b * T_ * st + (size_t)h * HS_;

    for (int it = tid; it < 512; it += 128) {
        const int r   = it >> 3;
        const int sgo = (it & 7) * 8;
        const uint32_t off = (uint32_t)(r * SWA_LDT + sgo) * 2;
        *reinterpret_cast<uint4*>(sm + (QH - sb) + off) =
            *reinterpret_cast<const uint4*>(baseh + (size_t)(qt * 64 + r) * st + sgo);
    }

    float o[8][4];
#pragma unroll
    for (int nt = 0; nt < 8; nt++)
#pragma unroll
        for (int e = 0; e < 4; e++) o[nt][e] = 0.0f;
    float mrow[2] = {-1e30f, -1e30f};
    float lrow[2] = {0.0f, 0.0f};

    const int ig0 = qt * 64 + w * 16 + (lane >> 2);
    const int ig1 = ig0 + 8;
    const int lo_q  = qt * 64 - (WIN_ - 1);
    const int kt_lo = lo_q > 0 ? (lo_q >> 6) : 0;

    for (int kt = kt_lo; kt <= qt; kt++) {
        __syncthreads();
        for (int it = tid; it < 512; it += 128) {
            const int r   = it >> 3;
            const int sgo = (it & 7) * 8;
            const size_t g = (size_t)(kt * 64 + r) * st + sgo;
            const uint32_t off = (uint32_t)(r * SWA_LDT + sgo) * 2;
            *reinterpret_cast<uint4*>(sm + (KH - sb) + off) =
                *reinterpret_cast<const uint4*>(baseh + C_ + g);
            *reinterpret_cast<uint4*>(sm + (VH - sb) + off) =
                *reinterpret_cast<const uint4*>(baseh + 2 * C_ + g);
        }
        __syncthreads();

        float s[8][4];
#pragma unroll
        for (int nt = 0; nt < 8; nt++)
#pragma unroll
            for (int e = 0; e < 4; e++) s[nt][e] = 0.0f;

#pragma unroll
        for (int ks = 0; ks < 4; ks++) {
            uint32_t qf[4];
            const uint32_t aoff =
                (uint32_t)((w * 16 + (lane & 15)) * SWA_LDT + ks * 16 + ((lane >> 4) << 3)) * 2;
            ldm4(qf, QH + aoff);
#pragma unroll
            for (int jc = 0; jc < 4; jc++) {
                uint32_t kh[4];
                const uint32_t boff =
                    (uint32_t)((jc * 16 + (lane & 7) + ((lane & 16) >> 1)) * SWA_LDT
                               + ks * 16 + (lane & 8)) * 2;
                ldm4(kh, KH + boff);
                mma_f16(s[jc * 2],     qf, kh);
                mma_f16(s[jc * 2 + 1], qf, kh + 2);
            }
        }

        const float sc = 0.125f;
        const int jb = kt * 64 + 2 * (lane & 3);
        float tmax0 = -1e30f, tmax1 = -1e30f;
#pragma unroll
        for (int nt = 0; nt < 8; nt++) {
            const int j0 = jb + nt * 8, j1 = j0 + 1;
            const bool v00 = (j0 <= ig0) && (ig0 - j0 < WIN_);
            const bool v01 = (j1 <= ig0) && (ig0 - j1 < WIN_);
            const bool v10 = (j0 <= ig1) && (ig1 - j0 < WIN_);
            const bool v11 = (j1 <= ig1) && (ig1 - j1 < WIN_);
            s[nt][0] *= sc; s[nt][1] *= sc; s[nt][2] *= sc; s[nt][3] *= sc;
            if (v00) tmax0 = fmaxf(tmax0, s[nt][0]);
            if (v01) tmax0 = fmaxf(tmax0, s[nt][1]);
            if (v10) tmax1 = fmaxf(tmax1, s[nt][2]);
            if (v11) tmax1 = fmaxf(tmax1, s[nt][3]);
        }
        tmax0 = fmaxf(tmax0, __shfl_xor_sync(0xffffffffu, tmax0, 1));
        tmax0 = fmaxf(tmax0, __shfl_xor_sync(0xffffffffu, tmax0, 2));
        tmax1 = fmaxf(tmax1, __shfl_xor_sync(0xffffffffu, tmax1, 1));
        tmax1 = fmaxf(tmax1, __shfl_xor_sync(0xffffffffu, tmax1, 2));

        const float mn0 = fmaxf(mrow[0], tmax0);
        const float mn1 = fmaxf(mrow[1], tmax1);
        const float es0 = __expf(mrow[0] - mn0);
        const float es1 = __expf(mrow[1] - mn1);
        mrow[0] = mn0; mrow[1] = mn1;

        uint32_t ph01[8], ph23[8];
        float ps0 = 0.0f, ps1 = 0.0f;
#pragma unroll
        for (int nt = 0; nt < 8; nt++) {
            const int j0 = jb + nt * 8, j1 = j0 + 1;
            const bool v00 = (j0 <= ig0) && (ig0 - j0 < WIN_);
            const bool v01 = (j1 <= ig0) && (ig0 - j1 < WIN_);
            const bool v10 = (j0 <= ig1) && (ig1 - j0 < WIN_);
            const bool v11 = (j1 <= ig1) && (ig1 - j1 < WIN_);
            const float p00 = v00 ? __expf(s[nt][0] - mn0) : 0.0f;
            const float p01 = v01 ? __expf(s[nt][1] - mn0) : 0.0f;
            const float p10 = v10 ? __expf(s[nt][2] - mn1) : 0.0f;
            const float p11 = v11 ? __expf(s[nt][3] - mn1) : 0.0f;
            ps0 += p00 + p01;
            ps1 += p10 + p11;
            __half2 h01 = __floats2half2_rn(p00, p01);
            __half2 h23 = __floats2half2_rn(p10, p11);
            ph01[nt] = *reinterpret_cast<uint32_t*>(&h01);
            ph23[nt] = *reinterpret_cast<uint32_t*>(&h23);
        }
        ps0 += __shfl_xor_sync(0xffffffffu, ps0, 1);
        ps0 += __shfl_xor_sync(0xffffffffu, ps0, 2);
        ps1 += __shfl_xor_sync(0xffffffffu, ps1, 1);
        ps1 += __shfl_xor_sync(0xffffffffu, ps1, 2);
        lrow[0] = lrow[0] * es0 + ps0;
        lrow[1] = lrow[1] * es1 + ps1;
#pragma unroll
        for (int nt = 0; nt < 8; nt++) {
            o[nt][0] *= es0; o[nt][1] *= es0;
            o[nt][2] *= es1; o[nt][3] *= es1;
        }

#pragma unroll
        for (int kj = 0; kj < 4; kj++) {
            uint32_t ah[4] = {ph01[2 * kj], ph23[2 * kj], ph01[2 * kj + 1], ph23[2 * kj + 1]};
#pragma unroll
            for (int dc = 0; dc < 4; dc++) {
                uint32_t vh[4];
                const uint32_t voff =
                    (uint32_t)((kj * 16 + (lane & 15)) * SWA_LDT
                               + dc * 16 + ((lane >> 4) << 3)) * 2;
                ldm4t(vh, VH + voff);
                mma_f16(o[dc * 2],     ah, vh);
                mma_f16(o[dc * 2 + 1], ah, vh + 2);
            }
        }
    }

    const float inv0 = 1.0f / lrow[0];
    const float inv1 = 1.0f / lrow[1];
    const size_t row0 = (size_t)b * T_ + qt * 64 + w * 16 + (lane >> 2);
    const int    colb = h * HS_ + 2 * (lane & 3);
#pragma unroll
    for (int nt = 0; nt < 8; nt++) {
        *reinterpret_cast<__half2*>(yq + row0 * C_ + colb + nt * 8) =
            __floats2half2_rn(o[nt][0] * inv0, o[nt][1] * inv0);
        *reinterpret_cast<__half2*>(yq + (row0 + 8) * C_ + colb + nt * 8) =
            __floats2half2_rn(o[nt][2] * inv1, o[nt][3] * inv1);
    }
}

// ---------------------------------------------------------------------------
extern "C" void kernel_launch(void* const* d_in, const int* in_sizes, int n_in,
                              void* d_out, int out_size)
{
    const float* x      = (const float*)d_in[0];
    const float* W_attn = (const float*)d_in[1];
    const float* W_proj = (const float*)d_in[2];
    float* out = (float*)d_out;

    __half *qkv, *xq, *yq, *wa, *wp;
    cudaGetSymbolAddress((void**)&qkv, g_qkv);
    cudaGetSymbolAddress((void**)&xq,  g_xq);
    cudaGetSymbolAddress((void**)&yq,  g_yq);
    cudaGetSymbolAddress((void**)&wa,  g_wa);
    cudaGetSymbolAddress((void**)&wp,  g_wp);

    cudaFuncSetAttribute(gemm_w64, cudaFuncAttributeMaxDynamicSharedMemorySize,
                         A64_SMEM);
    cudaFuncSetAttribute(gemm_proj, cudaFuncAttributeMaxDynamicSharedMemorySize,
                         P_SMEM);
    cudaFuncSetAttribute(swa_mma, cudaFuncAttributeMaxDynamicSharedMemorySize,
                         SWA_SMEM);

    const int M = B_ * T_;   // 4096

    // fused prep: x quant + both weight transposes, one launch
    prep_all<<<PREP_BLOCKS, 256>>>(x, W_attn, W_proj, xq, wa, wp);

    // qkv(q) = x @ W_attn  (M=4096, N=3072, K=1024): 2-stage, 3 CTAs/SM
    {
        dim3 g(3 * C_ / 128, M / 128);
        gemm_w64<<<g, 128, A64_SMEM>>>(xq, wa, qkv, M, 3 * C_, C_);
    }

    // fused SWA -> quantized y (pure 1-product)
    {
        dim3 g(T_ / 64, NH_, B_);
        swa_mma<<<g, 128, SWA_SMEM>>>(qkv, yq);
    }

    // out = y @ W_proj  (M=4096, N=1024, K=1024): 64x128 tiles, 512 CTAs
    {
        dim3 g(C_ / 128, M / 64);
        gemm_proj<<<g, 128, P_SMEM>>>(yq, wp, out, M, C_, C_);
    }
}